// round 16
// baseline (speedup 1.0000x reference)
#include <cuda_runtime.h>
#include <cstdint>

#define B_  2
#define S_  2048
#define D_  1024
#define H_  16

// head-major Q/K/V [(b*H+h)*S + s][dk]; X (B,S,D) row-major
__device__ __align__(256) float g_Q[(size_t)B_*S_*D_];
__device__ __align__(256) float g_K[(size_t)B_*S_*D_];
__device__ __align__(256) float g_V[(size_t)B_*S_*D_];
__device__ __align__(256) float g_X[(size_t)B_*S_*D_];

// ---------------------------------------------------------------------------
// helpers
// ---------------------------------------------------------------------------
__device__ __forceinline__ uint32_t f2tf32(float x){
    uint32_t r; asm("cvt.rna.tf32.f32 %0, %1;" : "=r"(r) : "f"(x)); return r;
}
__device__ __forceinline__ void mma_tf32(float* c, const uint32_t* a, const uint32_t* b){
    asm volatile("mma.sync.aligned.m16n8k8.row.col.f32.tf32.tf32.f32 "
        "{%0,%1,%2,%3}, {%4,%5,%6,%7}, {%8,%9}, {%0,%1,%2,%3};"
        : "+f"(c[0]),"+f"(c[1]),"+f"(c[2]),"+f"(c[3])
        : "r"(a[0]),"r"(a[1]),"r"(a[2]),"r"(a[3]),"r"(b[0]),"r"(b[1]));
}
__device__ __forceinline__ void mma_bf16(float* c, const uint32_t* a, const uint32_t* b){
    asm volatile("mma.sync.aligned.m16n8k16.row.col.f32.bf16.bf16.f32 "
        "{%0,%1,%2,%3}, {%4,%5,%6,%7}, {%8,%9}, {%0,%1,%2,%3};"
        : "+f"(c[0]),"+f"(c[1]),"+f"(c[2]),"+f"(c[3])
        : "r"(a[0]),"r"(a[1]),"r"(a[2]),"r"(a[3]),"r"(b[0]),"r"(b[1]));
}
// pack truncated-bf16 of (x,y): word = { hi16(y), hi16(x) }
__device__ __forceinline__ uint32_t prmt_hi(uint32_t x, uint32_t y){
    uint32_t r; asm("prmt.b32 %0, %1, %2, 0x7632;" : "=r"(r) : "r"(x), "r"(y)); return r;
}
// word = { bf16(hi), bf16(lo) }
__device__ __forceinline__ uint32_t bf16x2_rn(float hi, float lo){
    uint32_t r; asm("cvt.rn.bf16x2.f32 %0, %1, %2;" : "=r"(r) : "f"(hi), "f"(lo)); return r;
}
__device__ __forceinline__ uint16_t bf16_rn(float x){
    uint16_t r; asm("cvt.rn.bf16.f32 %0, %1;" : "=h"(r) : "f"(x)); return r;
}
__device__ __forceinline__ float trunc_bf(uint32_t xb){
    return __uint_as_float(xb & 0xffff0000u);
}

// ---------------------------------------------------------------------------
// BF16 3-term GEMM layout. Fragment-major, element = bf16x2 k-pair (u32).
#define FK_A  132
#define FM_AB 268
#define A_UB  2136
#define FK_B  68
#define FN_BB 140
#define B_UB  1112
#define BUFB_U32 (2*A_UB + 2*B_UB)     // 6496
#define SMEMB_BYTES (2*BUFB_U32*4)     // 51968

// TF32 1x layout (AV kernel)
#define FM_AT 532
#define A_UT  4248
#define FN_BT 276
#define B_UT  2200
#define BUFT_U32 (A_UT + B_UT)         // 6448
#define SMEMT_BYTES (2*BUFT_U32*4)     // 51584

// ---------------------------------------------------------------------------
// BF16 3-term tensor GEMM. BM=128, BN=64, BK=32, 256 thr (8 warps 4x2).
// MODE 6: z in {0,1,2}: C = in_z @ W_z -> g_Q/g_K/g_V head-major (M=4096,K=1024)
// MODE 3: C = g_X @ W_o -> out                                  (M=4096,K=1024)
// MODE 4: scores = Q @ K^T * 0.125 -> attn (per bh)             (M=2048,K=64)
// ---------------------------------------------------------------------------
template<int MODE>
__global__ void __launch_bounds__(256,2) mma_gemm_bf(
    const float* __restrict__ A0, const float* __restrict__ W0,
    const float* __restrict__ A1, const float* __restrict__ W1,
    const float* __restrict__ A2, const float* __restrict__ W2,
    float* __restrict__ C0)
{
    constexpr int KD  = (MODE==4)? 64 : 1024;
    constexpr int LDA = (MODE==4)? 64 : 1024;
    constexpr int LDB = (MODE==4)? 64 : 1024;

    extern __shared__ uint32_t smu[];

    const int tid  = threadIdx.x;
    const int warp = tid>>5, lane = tid&31;
    const int z    = (MODE==6)? blockIdx.z : 0;
    const int bh   = (MODE==4)? blockIdx.z : 0;

    const float* A; const float* Bm;
    if (MODE==6){ A = (z==0)?A0:(z==1)?A1:A2; Bm = (z==0)?W0:(z==1)?W1:W2; }
    else if (MODE==3){ A = g_X; Bm = W0; }
    else { A = g_Q + (size_t)bh*S_*64; Bm = g_K + (size_t)bh*S_*64; }

    const int mb = blockIdx.y*128, nb = blockIdx.x*64;

    int    abase[4]; size_t agoff[4];
    #pragma unroll
    for (int j=0;j<4;j++){
        int i = tid + j*256;
        int m = i>>3, kq = i&7;
        abase[j] = (m>>4)*FM_AB + (kq>>2)*FK_A
                 + (m&7)*16 + (kq&1)*8 + ((kq>>1)&1)*2 + ((m>>3)&1);
        agoff[j] = (size_t)(mb+m)*LDA + kq*4;
    }
    int    bbase[2]; size_t bgoff[2]; int bk[2];
    #pragma unroll
    for (int j=0;j<2;j++){
        int i = tid + j*256;
        if (MODE==4){
            int n = i>>3, kq = i&7;
            bbase[j] = (n>>3)*FN_BB + (kq>>2)*FK_B
                     + (n&7)*8 + (kq&1)*4 + ((kq>>1)&1);
            bgoff[j] = (size_t)(nb+n)*LDB + kq*4;
            bk[j] = 0;
        } else {
            int k = i>>4, nq = i&15;
            bbase[j] = nq;
            bgoff[j] = (size_t)k*LDB + nb + nq*4;
            bk[j] = k;
        }
    }

    float4 pa[4]; float4 pb[2];
    auto ldAB = [&](int kt){
        #pragma unroll
        for (int j=0;j<4;j++) pa[j] = *(const float4*)(A + agoff[j] + kt);
        #pragma unroll
        for (int j=0;j<2;j++){
            size_t off = (MODE==4) ? (bgoff[j] + kt) : (bgoff[j] + (size_t)kt*LDB);
            pb[j] = *(const float4*)(Bm + off);
        }
    };
    auto stAB = [&](uint32_t* buf){
        #pragma unroll
        for (int j=0;j<4;j++){
            uint32_t xb=__float_as_uint(pa[j].x), yb=__float_as_uint(pa[j].y);
            uint32_t zb=__float_as_uint(pa[j].z), wb=__float_as_uint(pa[j].w);
            uint32_t hi0 = prmt_hi(xb,yb), hi1 = prmt_hi(zb,wb);
            uint32_t lo0 = bf16x2_rn(pa[j].y - trunc_bf(yb), pa[j].x - trunc_bf(xb));
            uint32_t lo1 = bf16x2_rn(pa[j].w - trunc_bf(wb), pa[j].z - trunc_bf(zb));
            uint32_t* p = buf + abase[j];
            p[0]=hi0; p[4]=hi1;
            p[A_UB+0]=lo0; p[A_UB+4]=lo1;
        }
        uint32_t* bB = buf + 2*A_UB;
        #pragma unroll
        for (int j=0;j<2;j++){
            if (MODE==4){
                uint32_t xb=__float_as_uint(pb[j].x), yb=__float_as_uint(pb[j].y);
                uint32_t zb=__float_as_uint(pb[j].z), wb=__float_as_uint(pb[j].w);
                uint32_t* p = bB + bbase[j];
                p[0] = prmt_hi(xb,yb); p[2] = prmt_hi(zb,wb);
                p[B_UB+0] = bf16x2_rn(pb[j].y - trunc_bf(yb), pb[j].x - trunc_bf(xb));
                p[B_UB+2] = bf16x2_rn(pb[j].w - trunc_bf(wb), pb[j].z - trunc_bf(zb));
            } else {
                const int k = bk[j];
                const int kw = (k>>4)*FK_B + ((k>>1)&3)*2 + ((k>>3)&1);
                const int half = k&1;
                uint16_t* hb = (uint16_t*)bB;
                uint16_t* lb = (uint16_t*)(bB + B_UB);
                float v[4] = {pb[j].x, pb[j].y, pb[j].z, pb[j].w};
                #pragma unroll
                for (int c=0;c<4;c++){
                    int n = bbase[j]*4 + c;
                    int word = (n>>3)*FN_BB + (n&7)*8 + kw;
                    uint32_t vb = __float_as_uint(v[c]);
                    hb[(word<<1)|half] = (uint16_t)(vb>>16);
                    lb[(word<<1)|half] = bf16_rn(v[c] - trunc_bf(vb));
                }
            }
        }
    };

    float acc[2][4][4] = {};
    const int fm0 = (warp>>1)*2;
    const int fn0 = (warp&1)*4;

    ldAB(0);
    uint32_t* buf = smu;
    stAB(buf);
    __syncthreads();

    for (int kt = 0; kt < KD; kt += 32){
        const bool more = (kt + 32 < KD);
        if (more) ldAB(kt + 32);

        const uint32_t* bA = buf;
        const uint32_t* bB = buf + 2*A_UB;

        #pragma unroll
        for (int ks=0; ks<2; ks++){
            uint4 ah4[2], al4[2];
            #pragma unroll
            for (int mi=0;mi<2;mi++){
                const uint32_t* pA = bA + (fm0+mi)*FM_AB + ks*FK_A + lane*4;
                ah4[mi] = *(const uint4*)(pA);
                al4[mi] = *(const uint4*)(pA + A_UB);
            }
            #pragma unroll
            for (int ni=0;ni<4;ni++){
                const uint32_t* pB = bB + (fn0+ni)*FN_BB + ks*FK_B + lane*2;
                uint2 bh2 = *(const uint2*)(pB);
                uint2 bl2 = *(const uint2*)(pB + B_UB);
                #pragma unroll
                for (int mi=0;mi<2;mi++){
                    mma_bf16(acc[mi][ni], (const uint32_t*)&al4[mi], (const uint32_t*)&bh2);
                    mma_bf16(acc[mi][ni], (const uint32_t*)&ah4[mi], (const uint32_t*)&bl2);
                    mma_bf16(acc[mi][ni], (const uint32_t*)&ah4[mi], (const uint32_t*)&bh2);
                }
            }
        }

        uint32_t* nbuf = (buf == smu) ? smu + BUFB_U32 : smu;
        if (more) stAB(nbuf);
        __syncthreads();
        buf = nbuf;
    }

    // ---- epilogue ----
    const int grp = lane>>2, tig = lane&3;
    const int wm = (warp>>1)*32, wn = (warp&1)*32;
    #pragma unroll
    for (int mi=0;mi<2;mi++){
        #pragma unroll
        for (int ni=0;ni<4;ni++){
            const int r0 = mb + wm + mi*16 + grp;
            const int r1 = r0 + 8;
            const int c  = nb + wn + ni*8 + 2*tig;
            float2 v0 = make_float2(acc[mi][ni][0], acc[mi][ni][1]);
            float2 v1 = make_float2(acc[mi][ni][2], acc[mi][ni][3]);
            if (MODE==6){
                float* Cq = (z==0)? g_Q : (z==1)? g_K : g_V;
                const int h=c>>6, dk=c&63;
                const int b0=r0>>11, s0=r0&(S_-1);
                const int b1=r1>>11, s1=r1&(S_-1);
                *(float2*)&Cq[((((size_t)b0*H_+h)*S_+s0)<<6)+dk]=v0;
                *(float2*)&Cq[((((size_t)b1*H_+h)*S_+s1)<<6)+dk]=v1;
            } else if (MODE==3){
                *(float2*)&C0[(size_t)r0*D_+c]=v0;
                *(float2*)&C0[(size_t)r1*D_+c]=v1;
            } else { // MODE 4
                v0.x*=0.125f; v0.y*=0.125f; v1.x*=0.125f; v1.y*=0.125f;
                float* Cb = C0 + (size_t)bh*S_*S_;
                *(float2*)&Cb[(size_t)r0*S_+c]=v0;
                *(float2*)&Cb[(size_t)r1*S_+c]=v1;
            }
        }
    }
}

// ---------------------------------------------------------------------------
// AV GEMM: x = attn @ V, 1xTF32 (attn in [0,1]). M=2048, N=64, K=2048 per bh.
// ---------------------------------------------------------------------------
__global__ void __launch_bounds__(256,2) mma_av(const float* __restrict__ attn)
{
    constexpr int KD = 2048, LDA = 2048, LDB = 64;
    extern __shared__ uint32_t smu[];

    const int tid  = threadIdx.x;
    const int warp = tid>>5, lane = tid&31;
    const int bh   = blockIdx.z;

    const float* A  = attn + (size_t)bh*S_*S_;
    const float* Bm = g_V  + (size_t)bh*S_*64;
    const int mb = blockIdx.y*128, nb = 0;

    int    abase[4]; size_t agoff[4];
    #pragma unroll
    for (int j=0;j<4;j++){
        int i = tid + j*256;
        int m = i>>3, kq = i&7;
        abase[j] = (m>>4)*FM_AT + (kq>>1)*FK_A + 16*(m&7) + 2*(kq&1) + ((m>>3)&1);
        agoff[j] = (size_t)(mb+m)*LDA + kq*4;
    }
    int    bbase[2]; size_t bgoff[2];
    #pragma unroll
    for (int j=0;j<2;j++){
        int i = tid + j*256;
        int k = i>>4, nq = i&15;
        bbase[j] = (nq>>1)*FN_BT + (k>>3)*FK_B + 32*(nq&1) + 2*(k&3) + ((k>>2)&1);
        bgoff[j] = (size_t)k*LDB + nb + nq*4;
    }

    float4 pa[4]; float4 pb[2];
    auto ldAB = [&](int kt){
        #pragma unroll
        for (int j=0;j<4;j++) pa[j] = *(const float4*)(A  + agoff[j] + kt);
        #pragma unroll
        for (int j=0;j<2;j++) pb[j] = *(const float4*)(Bm + bgoff[j] + (size_t)kt*LDB);
    };
    auto stAB = [&](uint32_t* buf){
        #pragma unroll
        for (int j=0;j<4;j++){
            uint32_t* p = buf + abase[j];
            p[0] =f2tf32(pa[j].x); p[4] =f2tf32(pa[j].y);
            p[8] =f2tf32(pa[j].z); p[12]=f2tf32(pa[j].w);
        }
        uint32_t* bB = buf + A_UT;
        #pragma unroll
        for (int j=0;j<2;j++){
            uint32_t* p = bB + bbase[j];
            p[0] =f2tf32(pb[j].x); p[8] =f2tf32(pb[j].y);
            p[16]=f2tf32(pb[j].z); p[24]=f2tf32(pb[j].w);
        }
    };

    float acc[2][4][4] = {};
    const int fm0 = (warp>>1)*2;
    const int fn0 = (warp&1)*4;

    ldAB(0);
    uint32_t* buf = smu;
    stAB(buf);
    __syncthreads();

    for (int kt = 0; kt < KD; kt += 32){
        const bool more = (kt + 32 < KD);
        if (more) ldAB(kt + 32);

        const uint32_t* bA = buf;
        const uint32_t* bB = buf + A_UT;

        #pragma unroll
        for (int ks=0; ks<4; ks++){
            uint4 ah4[2];
            #pragma unroll
            for (int mi=0;mi<2;mi++)
                ah4[mi] = *(const uint4*)(bA + (fm0+mi)*FM_AT + ks*FK_A + lane*4);
            #pragma unroll
            for (int ni=0;ni<4;ni++){
                uint2 bh2 = *(const uint2*)(bB + (fn0+ni)*FN_BT + ks*FK_B + lane*2);
                #pragma unroll
                for (int mi=0;mi<2;mi++)
                    mma_tf32(acc[mi][ni], (const uint32_t*)&ah4[mi], (const uint32_t*)&bh2);
            }
        }

        uint32_t* nbuf = (buf == smu) ? smu + BUFT_U32 : smu;
        if (more) stAB(nbuf);
        __syncthreads();
        buf = nbuf;
    }

    const int grp = lane>>2, tig = lane&3;
    const int wm = (warp>>1)*32, wn = (warp&1)*32;
    const int b0 = bh>>4, h = bh&15;
    #pragma unroll
    for (int mi=0;mi<2;mi++){
        #pragma unroll
        for (int ni=0;ni<4;ni++){
            const int r0 = mb + wm + mi*16 + grp;
            const int r1 = r0 + 8;
            const int c  = wn + ni*8 + 2*tig;
            *(float2*)&g_X[((size_t)(b0*S_+r0))*D_ + h*64 + c] =
                make_float2(acc[mi][ni][0], acc[mi][ni][1]);
            *(float2*)&g_X[((size_t)(b0*S_+r1))*D_ + h*64 + c] =
                make_float2(acc[mi][ni][2], acc[mi][ni][3]);
        }
    }
}

// ---------------------------------------------------------------------------
// Softmax v2: block per (q,b). Mask row converted ONCE into smem select
// values (masked ? -1e9 : +BIG, applied via fminf). Then each warp owns
// whole head-rows (heads warp and warp+8): the 2048-wide row lives in
// registers (16 x float4 per lane), max/sum are warp shuffles only — no
// __syncthreads in the head loop.
// ---------------------------------------------------------------------------
__global__ void __launch_bounds__(256) softmax_kernel(const int* __restrict__ mask,
                                                      float* __restrict__ attn)
{
    __shared__ float msel[S_];

    const int q = blockIdx.x, b = blockIdx.y;
    const int tid  = threadIdx.x;
    const int warp = tid>>5, lane = tid&31;

    // mask row -> select values in smem (once per block)
    const int4* m4 = (const int4*)(mask + ((size_t)b*S_ + q)*S_);
    #pragma unroll
    for (int j=0;j<2;j++){
        int4 mm = m4[tid + j*256];
        float4 s;
        s.x = mm.x ? 3.0e38f : -1e9f;
        s.y = mm.y ? 3.0e38f : -1e9f;
        s.z = mm.z ? 3.0e38f : -1e9f;
        s.w = mm.w ? 3.0e38f : -1e9f;
        ((float4*)msel)[tid + j*256] = s;
    }
    __syncthreads();

    const float4* ms4 = (const float4*)msel;

    #pragma unroll
    for (int hh=0; hh<2; ++hh){
        const int h = warp + hh*8;
        float4* g = (float4*)(attn + (((size_t)(b*H_+h))*S_ + q)*S_);

        float4 v[16];
        #pragma unroll
        for (int i=0;i<16;i++) v[i] = g[i*32 + lane];

        // apply mask via fminf with select values (exact -1e9 for masked)
        #pragma unroll
        for (int i=0;i<16;i++){
            float4 m = ms4[i*32 + lane];
            v[i].x = fminf(v[i].x, m.x);
            v[i].y = fminf(v[i].y, m.y);
            v[i].z = fminf(v[i].z, m.z);
            v[i].w = fminf(v[i].w, m.w);
        }

        float mx = -3.0e38f;
        #pragma unroll
        for (int i=0;i<16;i++)
            mx = fmaxf(mx, fmaxf(fmaxf(v[i].x,v[i].y), fmaxf(v[i].z,v[i].w)));
        #pragma unroll
        for (int o=16;o;o>>=1) mx = fmaxf(mx, __shfl_xor_sync(0xffffffffu, mx, o));

        float sum = 0.f;
        #pragma unroll
        for (int i=0;i<16;i++){
            v[i].x = __expf(v[i].x - mx);
            v[i].y = __expf(v[i].y - mx);
            v[i].z = __expf(v[i].z - mx);
            v[i].w = __expf(v[i].w - mx);
            sum += v[i].x + v[i].y + v[i].z + v[i].w;
        }
        #pragma unroll
        for (int o=16;o;o>>=1) sum += __shfl_xor_sync(0xffffffffu, sum, o);
        const float inv = 1.0f / sum;

        #pragma unroll
        for (int i=0;i<16;i++){
            v[i].x *= inv; v[i].y *= inv; v[i].z *= inv; v[i].w *= inv;
            g[i*32 + lane] = v[i];
        }
    }
}

// ---------------------------------------------------------------------------
// Launch
// ---------------------------------------------------------------------------
extern "C" void kernel_launch(void* const* d_in, const int* in_sizes, int n_in,
                              void* d_out, int out_size)
{
    const float* query = (const float*)d_in[0];
    const float* key   = (const float*)d_in[1];
    const float* value = (const float*)d_in[2];
    const int*   mask  = (const int*)  d_in[3];
    const float* Wq    = (const float*)d_in[4];
    const float* Wk    = (const float*)d_in[5];
    const float* Wv    = (const float*)d_in[6];
    const float* Wo    = (const float*)d_in[7];
    float* out  = (float*)d_out;
    float* attn = out + (size_t)B_*S_*D_;

    cudaFuncSetAttribute(mma_gemm_bf<3>, cudaFuncAttributeMaxDynamicSharedMemorySize, SMEMB_BYTES);
    cudaFuncSetAttribute(mma_gemm_bf<4>, cudaFuncAttributeMaxDynamicSharedMemorySize, SMEMB_BYTES);
    cudaFuncSetAttribute(mma_gemm_bf<6>, cudaFuncAttributeMaxDynamicSharedMemorySize, SMEMB_BYTES);
    cudaFuncSetAttribute(mma_av,         cudaFuncAttributeMaxDynamicSharedMemorySize, SMEMT_BYTES);

    // fused Q/K/V projections (3-term bf16)
    mma_gemm_bf<6><<<dim3(D_/64,(B_*S_)/128,3), 256, SMEMB_BYTES>>>(
        query, Wq, key, Wk, value, Wv, nullptr);

    // scores (3-term bf16)
    mma_gemm_bf<4><<<dim3(S_/64, S_/128, B_*H_), 256, SMEMB_BYTES>>>(
        nullptr, nullptr, nullptr, nullptr, nullptr, nullptr, attn);

    softmax_kernel<<<dim3(S_, B_), 256>>>(mask, attn);

    // x = attn @ V (1xTF32)
    mma_av<<<dim3(1, S_/128, B_*H_), 256, SMEMT_BYTES>>>(attn);

    // out = x @ W_o (3-term bf16)
    mma_gemm_bf<3><<<dim3(D_/64,(B_*S_)/128,1), 256, SMEMB_BYTES>>>(
        nullptr, Wo, nullptr, nullptr, nullptr, nullptr, out);
}